// round 5
// baseline (speedup 1.0000x reference)
#include <cuda_runtime.h>
#include <cuda_bf16.h>
#include <math.h>

#define N_NODES 100000
#define N_EDGES 20000
#define N_INC   800000
#define D_IN    256
#define D_HID   16
#define D_OUT   40
#define PAD_E   128
#define PAD_V   64
#define NT      1024

// ---------------- scratch (device globals) ----------------
__device__ float g_XW1[(size_t)N_NODES * D_HID];
__device__ float g_e1 [(size_t)N_EDGES * D_HID];
__device__ float g_XW2[(size_t)N_NODES * D_OUT];
__device__ float g_e2 [(size_t)N_EDGES * D_OUT];
__device__ int   g_cnt_e[N_EDGES];
__device__ int   g_cnt_v[N_NODES];
__device__ int   g_buf_e[(size_t)N_EDGES * PAD_E];
__device__ int   g_buf_v[(size_t)N_NODES * PAD_V];
__device__ unsigned g_bar_count;   // zero-init; self-cleaning across calls
__device__ unsigned g_bar_sense;

// ---------------- software grid barrier (all blocks resident: grid = #SMs) ----
__device__ __forceinline__ void grid_barrier() {
    __syncthreads();
    if (threadIdx.x == 0) {
        __threadfence();
        unsigned sense = atomicAdd(&g_bar_sense, 0u);      // read BEFORE arriving
        unsigned arrived = atomicAdd(&g_bar_count, 1u);
        if (arrived == gridDim.x - 1) {
            g_bar_count = 0;
            __threadfence();
            atomicAdd(&g_bar_sense, 1u);                   // release
        } else {
            while (atomicAdd(&g_bar_sense, 0u) == sense) { }
        }
        __threadfence();
    }
    __syncthreads();
}

__global__ void __launch_bounds__(NT, 1)
hypermsg_persistent(const float* __restrict__ H,  const float* __restrict__ w,
                    const int*   __restrict__ ni, const int*   __restrict__ ei,
                    const float* __restrict__ W1, const float* __restrict__ b1,
                    const float* __restrict__ W2, const float* __restrict__ b2,
                    float* __restrict__ out) {
    __shared__ float sW[D_IN * D_HID];     // 16 KB; reused by phase 3
    __shared__ float sB[D_HID];

    const int tid     = threadIdx.x;
    const int gthread = blockIdx.x * NT + tid;
    const int nthread = gridDim.x * NT;
    const int gwarp   = gthread >> 5;
    const int nwarps  = nthread >> 5;
    const int lane    = tid & 31;

    // ---- P0: zero counters ----
    {
        int zc = (N_EDGES + N_NODES) / 4;
        for (int i = gthread; i < zc; i += nthread) {
            int4 z = make_int4(0, 0, 0, 0);
            if (i < N_EDGES / 4) reinterpret_cast<int4*>(g_cnt_e)[i] = z;
            else reinterpret_cast<int4*>(g_cnt_v)[i - N_EDGES / 4] = z;
        }
    }
    // load W1 into shared while here (independent of counters)
    for (int i = tid; i < D_IN * D_HID; i += NT) sW[i] = W1[i];
    grid_barrier();

    // ---- P1: fill buckets + GEMM1 ----
    for (int row = gthread; row < N_NODES; row += nthread) {
        float acc[D_HID];
#pragma unroll
        for (int j = 0; j < D_HID; j++) acc[j] = 0.f;
        const float4* hp = reinterpret_cast<const float4*>(H + (size_t)row * D_IN);
#pragma unroll 4
        for (int k4 = 0; k4 < D_IN / 4; k4++) {
            float4 hv = hp[k4];
            const float* wr = &sW[k4 * 4 * D_HID];
            float xs[4] = {hv.x, hv.y, hv.z, hv.w};
#pragma unroll
            for (int c = 0; c < 4; c++) {
                const float4* w4 = reinterpret_cast<const float4*>(wr + c * D_HID);
                float4 wa = w4[0], wb = w4[1], wc = w4[2], wd = w4[3];
                float x = xs[c];
                acc[0]  += x * wa.x;  acc[1]  += x * wa.y;  acc[2]  += x * wa.z;  acc[3]  += x * wa.w;
                acc[4]  += x * wb.x;  acc[5]  += x * wb.y;  acc[6]  += x * wb.z;  acc[7]  += x * wb.w;
                acc[8]  += x * wc.x;  acc[9]  += x * wc.y;  acc[10] += x * wc.z;  acc[11] += x * wc.w;
                acc[12] += x * wd.x;  acc[13] += x * wd.y;  acc[14] += x * wd.z;  acc[15] += x * wd.w;
            }
        }
        float4* op = reinterpret_cast<float4*>(g_XW1 + (size_t)row * D_HID);
        op[0] = make_float4(acc[0],  acc[1],  acc[2],  acc[3]);
        op[1] = make_float4(acc[4],  acc[5],  acc[6],  acc[7]);
        op[2] = make_float4(acc[8],  acc[9],  acc[10], acc[11]);
        op[3] = make_float4(acc[12], acc[13], acc[14], acc[15]);
    }
    for (int i = gthread; i < N_INC; i += nthread) {
        int v = __ldg(&ni[i]);
        int e = __ldg(&ei[i]);
        int se = atomicAdd(&g_cnt_e[e], 1);
        if (se < PAD_E) g_buf_e[(size_t)e * PAD_E + se] = v;
        int sv = atomicAdd(&g_cnt_v[v], 1);
        if (sv < PAD_V) g_buf_v[(size_t)v * PAD_V + sv] = e;
    }
    grid_barrier();

    // ---- P2: edge gather 1 (4-lane float4 groups, 8 members/iter) ----
    {
        int g = lane >> 2, c = lane & 3;
        for (int e = gwarp; e < N_EDGES; e += nwarps) {
            int cnt = min(g_cnt_e[e], PAD_E);
            const int* buf = g_buf_e + (size_t)e * PAD_E;
            float4 acc = make_float4(0.f, 0.f, 0.f, 0.f);
            float wsum = 0.f;
            int mb = 0;
            for (; mb + 8 <= cnt; mb += 8) {
                int v = __ldg(&buf[mb + g]);
                float wv = __ldg(&w[v]);
                float4 x = __ldg(reinterpret_cast<const float4*>(g_XW1) + (size_t)v * 4 + c);
                acc.x += wv * x.x; acc.y += wv * x.y; acc.z += wv * x.z; acc.w += wv * x.w;
                wsum += wv;
            }
            if (mb + g < cnt) {
                int v = __ldg(&buf[mb + g]);
                float wv = __ldg(&w[v]);
                float4 x = __ldg(reinterpret_cast<const float4*>(g_XW1) + (size_t)v * 4 + c);
                acc.x += wv * x.x; acc.y += wv * x.y; acc.z += wv * x.z; acc.w += wv * x.w;
                wsum += wv;
            }
#pragma unroll
            for (int st = 4; st < 32; st <<= 1) {
                acc.x += __shfl_xor_sync(0xFFFFFFFFu, acc.x, st);
                acc.y += __shfl_xor_sync(0xFFFFFFFFu, acc.y, st);
                acc.z += __shfl_xor_sync(0xFFFFFFFFu, acc.z, st);
                acc.w += __shfl_xor_sync(0xFFFFFFFFu, acc.w, st);
                wsum  += __shfl_xor_sync(0xFFFFFFFFu, wsum,  st);
            }
            float inv = __frcp_rn(fmaxf(wsum, 1e-6f));
            if (g == 0) {
                float4 r = make_float4(acc.x * inv, acc.y * inv, acc.z * inv, acc.w * inv);
                reinterpret_cast<float4*>(g_e1)[(size_t)e * 4 + c] = r;
            }
        }
    }
    grid_barrier();

    // ---- P3: node gather 1 + relu + GEMM2 ----
    for (int i = tid; i < D_HID * D_OUT; i += NT) sW[i] = W2[i];
    if (tid < D_HID) sB[tid] = b1[tid];
    __syncthreads();
    {
        int g = lane >> 2, c = lane & 3;
        for (int v = gwarp; v < N_NODES; v += nwarps) {
            int cnt = min(g_cnt_v[v], PAD_V);
            const int* buf = g_buf_v + (size_t)v * PAD_V;
            float4 acc = make_float4(0.f, 0.f, 0.f, 0.f);
            int mb = 0;
            for (; mb + 8 <= cnt; mb += 8) {
                int e0 = __ldg(&buf[mb + g]);
                float4 x = __ldg(reinterpret_cast<const float4*>(g_e1) + (size_t)e0 * 4 + c);
                acc.x += x.x; acc.y += x.y; acc.z += x.z; acc.w += x.w;
            }
            if (mb + g < cnt) {
                int e0 = __ldg(&buf[mb + g]);
                float4 x = __ldg(reinterpret_cast<const float4*>(g_e1) + (size_t)e0 * 4 + c);
                acc.x += x.x; acc.y += x.y; acc.z += x.z; acc.w += x.w;
            }
#pragma unroll
            for (int st = 4; st < 32; st <<= 1) {
                acc.x += __shfl_xor_sync(0xFFFFFFFFu, acc.x, st);
                acc.y += __shfl_xor_sync(0xFFFFFFFFu, acc.y, st);
                acc.z += __shfl_xor_sync(0xFFFFFFFFu, acc.z, st);
                acc.w += __shfl_xor_sync(0xFFFFFFFFu, acc.w, st);
            }
            float invd = __frcp_rn(fmaxf((float)cnt, 1.f));
            // lane (any g) holds x[4c..4c+3]
            float4 xx;
            xx.x = fmaxf(acc.x * invd + sB[c * 4 + 0], 0.f);
            xx.y = fmaxf(acc.y * invd + sB[c * 4 + 1], 0.f);
            xx.z = fmaxf(acc.z * invd + sB[c * 4 + 2], 0.f);
            xx.w = fmaxf(acc.w * invd + sB[c * 4 + 3], 0.f);

            float o0 = 0.f, o1 = 0.f;
#pragma unroll
            for (int k = 0; k < D_HID; k++) {
                int src = k >> 2;             // lane with c == k/4 (g==0 slice)
                float comp = (k & 3) == 0 ? xx.x : (k & 3) == 1 ? xx.y : (k & 3) == 2 ? xx.z : xx.w;
                float xk = __shfl_sync(0xFFFFFFFFu, comp, src);
                o0 += xk * sW[k * D_OUT + lane];
                if (lane < D_OUT - 32) o1 += xk * sW[k * D_OUT + 32 + lane];
            }
            g_XW2[(size_t)v * D_OUT + lane] = o0;
            if (lane < D_OUT - 32) g_XW2[(size_t)v * D_OUT + 32 + lane] = o1;
        }
    }
    grid_barrier();

    // ---- P4: edge gather 2 (10-lane float4 groups, 3 members/iter) ----
    {
        int grp = lane / 10;          // 0..2 active, 3 = idle
        int gc  = lane - grp * 10;    // float4 slot 0..9
        bool act = lane < 30;
        for (int e = gwarp; e < N_EDGES; e += nwarps) {
            int cnt = min(g_cnt_e[e], PAD_E);
            const int* buf = g_buf_e + (size_t)e * PAD_E;
            float4 acc = make_float4(0.f, 0.f, 0.f, 0.f);
            float wsum = 0.f;
            int mb = 0;
            for (; mb + 3 <= cnt; mb += 3) {
                if (act) {
                    int v = __ldg(&buf[mb + grp]);
                    float wv = __ldg(&w[v]);
                    float4 x = __ldg(reinterpret_cast<const float4*>(g_XW2) + (size_t)v * 10 + gc);
                    acc.x += wv * x.x; acc.y += wv * x.y; acc.z += wv * x.z; acc.w += wv * x.w;
                    wsum += wv;
                }
            }
            if (act && grp < cnt - mb) {
                int v = __ldg(&buf[mb + grp]);
                float wv = __ldg(&w[v]);
                float4 x = __ldg(reinterpret_cast<const float4*>(g_XW2) + (size_t)v * 10 + gc);
                acc.x += wv * x.x; acc.y += wv * x.y; acc.z += wv * x.z; acc.w += wv * x.w;
                wsum += wv;
            }
            // reduce across 3 groups -> lanes 0..9
            acc.x += __shfl_sync(0xFFFFFFFFu, acc.x, lane + 10) + __shfl_sync(0xFFFFFFFFu, acc.x, lane + 20);
            acc.y += __shfl_sync(0xFFFFFFFFu, acc.y, lane + 10) + __shfl_sync(0xFFFFFFFFu, acc.y, lane + 20);
            acc.z += __shfl_sync(0xFFFFFFFFu, acc.z, lane + 10) + __shfl_sync(0xFFFFFFFFu, acc.z, lane + 20);
            acc.w += __shfl_sync(0xFFFFFFFFu, acc.w, lane + 10) + __shfl_sync(0xFFFFFFFFu, acc.w, lane + 20);
            wsum  += __shfl_sync(0xFFFFFFFFu, wsum,  lane + 10) + __shfl_sync(0xFFFFFFFFu, wsum,  lane + 20);
            if (lane < 10) {
                float inv = __frcp_rn(fmaxf(wsum, 1e-6f));
                float4 r = make_float4(acc.x * inv, acc.y * inv, acc.z * inv, acc.w * inv);
                reinterpret_cast<float4*>(g_e2)[(size_t)e * 10 + lane] = r;
            }
        }
    }
    grid_barrier();

    // ---- P5: node gather 2 + bias + log_softmax -> out ----
    {
        int grp = lane / 10;
        int gc  = lane - grp * 10;
        bool act = lane < 30;
        for (int v = gwarp; v < N_NODES; v += nwarps) {
            int cnt = min(g_cnt_v[v], PAD_V);
            const int* buf = g_buf_v + (size_t)v * PAD_V;
            float4 acc = make_float4(0.f, 0.f, 0.f, 0.f);
            int mb = 0;
            for (; mb + 3 <= cnt; mb += 3) {
                if (act) {
                    int e0 = __ldg(&buf[mb + grp]);
                    float4 x = __ldg(reinterpret_cast<const float4*>(g_e2) + (size_t)e0 * 10 + gc);
                    acc.x += x.x; acc.y += x.y; acc.z += x.z; acc.w += x.w;
                }
            }
            if (act && grp < cnt - mb) {
                int e0 = __ldg(&buf[mb + grp]);
                float4 x = __ldg(reinterpret_cast<const float4*>(g_e2) + (size_t)e0 * 10 + gc);
                acc.x += x.x; acc.y += x.y; acc.z += x.z; acc.w += x.w;
            }
            acc.x += __shfl_sync(0xFFFFFFFFu, acc.x, lane + 10) + __shfl_sync(0xFFFFFFFFu, acc.x, lane + 20);
            acc.y += __shfl_sync(0xFFFFFFFFu, acc.y, lane + 10) + __shfl_sync(0xFFFFFFFFu, acc.y, lane + 20);
            acc.z += __shfl_sync(0xFFFFFFFFu, acc.z, lane + 10) + __shfl_sync(0xFFFFFFFFu, acc.z, lane + 20);
            acc.w += __shfl_sync(0xFFFFFFFFu, acc.w, lane + 10) + __shfl_sync(0xFFFFFFFFu, acc.w, lane + 20);

            float invd = __frcp_rn(fmaxf((float)cnt, 1.f));
            float4 val = make_float4(-INFINITY, -INFINITY, -INFINITY, -INFINITY);
            if (lane < 10) {
                float4 bb = __ldg(reinterpret_cast<const float4*>(b2) + lane);
                val.x = acc.x * invd + bb.x;
                val.y = acc.y * invd + bb.y;
                val.z = acc.z * invd + bb.z;
                val.w = acc.w * invd + bb.w;
            }
            float mx = fmaxf(fmaxf(val.x, val.y), fmaxf(val.z, val.w));  // -INF for lanes>=10
#pragma unroll
            for (int st = 8; st > 0; st >>= 1)
                mx = fmaxf(mx, __shfl_xor_sync(0xFFFFFFFFu, mx, st));    // lanes 0..15 all-reduce
            float s = (lane < 10)
                ? (__expf(val.x - mx) + __expf(val.y - mx) + __expf(val.z - mx) + __expf(val.w - mx))
                : 0.f;
#pragma unroll
            for (int st = 8; st > 0; st >>= 1)
                s += __shfl_xor_sync(0xFFFFFFFFu, s, st);
            float lse = mx + __logf(s);
            if (lane < 10) {
                float4 r = make_float4(val.x - lse, val.y - lse, val.z - lse, val.w - lse);
                reinterpret_cast<float4*>(out)[(size_t)v * 10 + lane] = r;
            }
        }
    }
}

// ---------------- launch ----------------
extern "C" void kernel_launch(void* const* d_in, const int* in_sizes, int n_in,
                              void* d_out, int out_size) {
    const float* H   = (const float*)d_in[0];
    const float* w   = (const float*)d_in[1];
    const int*   ni  = (const int*)  d_in[2];
    const int*   ei  = (const int*)  d_in[3];
    const float* W1  = (const float*)d_in[4];
    const float* b1  = (const float*)d_in[5];
    const float* W2  = (const float*)d_in[6];
    const float* b2  = (const float*)d_in[7];
    float*       out = (float*)d_out;

    int dev = 0, nsm = 148;
    cudaGetDevice(&dev);
    cudaDeviceGetAttribute(&nsm, cudaDevAttrMultiProcessorCount, dev);

    hypermsg_persistent<<<nsm, NT>>>(H, w, ni, ei, W1, b1, W2, b2, out);
}

// round 6
// speedup vs baseline: 1.1325x; 1.1325x over previous
#include <cuda_runtime.h>
#include <cuda_bf16.h>
#include <math.h>

#define N_NODES 100000
#define N_EDGES 20000
#define N_INC   800000
#define D_IN    256
#define D_HID   16
#define D_OUT   40
#define PAD_E   128
#define PAD_V   64

// ---------------- scratch (device globals) ----------------
__device__ float g_XW1[(size_t)N_NODES * D_HID];
__device__ float g_e1 [(size_t)N_EDGES * D_HID];
__device__ float g_XW2[(size_t)N_NODES * D_OUT];
__device__ float g_e2 [(size_t)N_EDGES * D_OUT];
__device__ int   g_cnt_e[N_EDGES];
__device__ int   g_cnt_v[N_NODES];
__device__ int   g_buf_e[(size_t)N_EDGES * PAD_E];
__device__ int   g_buf_v[(size_t)N_NODES * PAD_V];

// ---------------- zero counters ----------------
#define ZC ((N_EDGES + N_NODES) / 4)
__global__ void zero_cnt_kernel() {
    int i = blockIdx.x * blockDim.x + threadIdx.x;
    if (i >= ZC) return;
    int4 z = make_int4(0, 0, 0, 0);
    if (i < N_EDGES / 4) reinterpret_cast<int4*>(g_cnt_e)[i] = z;
    else reinterpret_cast<int4*>(g_cnt_v)[i - N_EDGES / 4] = z;
}

// ---------------- build padded buckets ----------------
__global__ void fill_kernel(const int* __restrict__ ni, const int* __restrict__ ei) {
    int i = blockIdx.x * blockDim.x + threadIdx.x;
    if (i >= N_INC) return;
    int v = __ldg(&ni[i]);
    int e = __ldg(&ei[i]);
    int se = atomicAdd(&g_cnt_e[e], 1);
    if (se < PAD_E) g_buf_e[(size_t)e * PAD_E + se] = v;
    int sv = atomicAdd(&g_cnt_v[v], 1);
    if (sv < PAD_V) g_buf_v[(size_t)v * PAD_V + sv] = e;
}

// ---------------- GEMM1: XW1 = H @ W1  (100000x256 @ 256x16) ----------------
__global__ void gemm1_kernel(const float* __restrict__ H, const float* __restrict__ W1) {
    __shared__ float sW[D_IN * D_HID];
    for (int i = threadIdx.x; i < D_IN * D_HID; i += blockDim.x) sW[i] = W1[i];
    __syncthreads();

    int row = blockIdx.x * blockDim.x + threadIdx.x;
    if (row >= N_NODES) return;

    float acc[D_HID];
#pragma unroll
    for (int j = 0; j < D_HID; j++) acc[j] = 0.f;

    const float4* hp = reinterpret_cast<const float4*>(H + (size_t)row * D_IN);
#pragma unroll 4
    for (int k4 = 0; k4 < D_IN / 4; k4++) {
        float4 hv = hp[k4];
        const float* wr = &sW[k4 * 4 * D_HID];
        float xs[4] = {hv.x, hv.y, hv.z, hv.w};
#pragma unroll
        for (int c = 0; c < 4; c++) {
            const float4* w4 = reinterpret_cast<const float4*>(wr + c * D_HID);
            float4 wa = w4[0], wb = w4[1], wc = w4[2], wd = w4[3];
            float x = xs[c];
            acc[0]  += x * wa.x;  acc[1]  += x * wa.y;  acc[2]  += x * wa.z;  acc[3]  += x * wa.w;
            acc[4]  += x * wb.x;  acc[5]  += x * wb.y;  acc[6]  += x * wb.z;  acc[7]  += x * wb.w;
            acc[8]  += x * wc.x;  acc[9]  += x * wc.y;  acc[10] += x * wc.z;  acc[11] += x * wc.w;
            acc[12] += x * wd.x;  acc[13] += x * wd.y;  acc[14] += x * wd.z;  acc[15] += x * wd.w;
        }
    }
    float4* op = reinterpret_cast<float4*>(g_XW1 + (size_t)row * D_HID);
    op[0] = make_float4(acc[0],  acc[1],  acc[2],  acc[3]);
    op[1] = make_float4(acc[4],  acc[5],  acc[6],  acc[7]);
    op[2] = make_float4(acc[8],  acc[9],  acc[10], acc[11]);
    op[3] = make_float4(acc[12], acc[13], acc[14], acc[15]);
}

// ---------------- edge gather 1: warp/edge, 8 groups x 4-lane float4 ---------
// per iteration: 8 members; 3 LDG instructions total (idx, w, row-float4)
__global__ void edge_gather1_kernel(const float* __restrict__ w) {
    int warp = (blockIdx.x * blockDim.x + threadIdx.x) >> 5;
    int lane = threadIdx.x & 31;
    if (warp >= N_EDGES) return;
    int e = warp;
    int cnt = min(__ldg(&g_cnt_e[e]), PAD_E);
    int g = lane >> 2, c = lane & 3;

    const int* buf = g_buf_e + (size_t)e * PAD_E;
    float4 acc = make_float4(0.f, 0.f, 0.f, 0.f);
    float wsum = 0.f;
    int mb = 0;
    for (; mb + 8 <= cnt; mb += 8) {
        int v = __ldg(&buf[mb + g]);
        float wv = __ldg(&w[v]);
        float4 x = __ldg(reinterpret_cast<const float4*>(g_XW1) + (size_t)v * 4 + c);
        acc.x += wv * x.x; acc.y += wv * x.y; acc.z += wv * x.z; acc.w += wv * x.w;
        wsum += wv;
    }
    if (mb + g < cnt) {
        int v = __ldg(&buf[mb + g]);
        float wv = __ldg(&w[v]);
        float4 x = __ldg(reinterpret_cast<const float4*>(g_XW1) + (size_t)v * 4 + c);
        acc.x += wv * x.x; acc.y += wv * x.y; acc.z += wv * x.z; acc.w += wv * x.w;
        wsum += wv;
    }
#pragma unroll
    for (int st = 4; st < 32; st <<= 1) {
        acc.x += __shfl_xor_sync(0xFFFFFFFFu, acc.x, st);
        acc.y += __shfl_xor_sync(0xFFFFFFFFu, acc.y, st);
        acc.z += __shfl_xor_sync(0xFFFFFFFFu, acc.z, st);
        acc.w += __shfl_xor_sync(0xFFFFFFFFu, acc.w, st);
        wsum  += __shfl_xor_sync(0xFFFFFFFFu, wsum,  st);
    }
    float inv = __frcp_rn(fmaxf(wsum, 1e-6f));
    if (g == 0) {
        float4 r = make_float4(acc.x * inv, acc.y * inv, acc.z * inv, acc.w * inv);
        reinterpret_cast<float4*>(g_e1)[(size_t)e * 4 + c] = r;
    }
}

// ---------------- node gather 1 + relu + GEMM2 (warp/node, same grouping) ----
__global__ void node_gather1_gemm2_kernel(const float* __restrict__ W2,
                                          const float* __restrict__ b1) {
    __shared__ float sW[D_HID * D_OUT];
    __shared__ float sB[D_HID];
    for (int i = threadIdx.x; i < D_HID * D_OUT; i += blockDim.x) sW[i] = W2[i];
    if (threadIdx.x < D_HID) sB[threadIdx.x] = b1[threadIdx.x];
    __syncthreads();

    int warp = (blockIdx.x * blockDim.x + threadIdx.x) >> 5;
    int lane = threadIdx.x & 31;
    if (warp >= N_NODES) return;
    int v = warp;
    int cnt = min(__ldg(&g_cnt_v[v]), PAD_V);
    int g = lane >> 2, c = lane & 3;

    const int* buf = g_buf_v + (size_t)v * PAD_V;
    float4 acc = make_float4(0.f, 0.f, 0.f, 0.f);
    int mb = 0;
    for (; mb + 8 <= cnt; mb += 8) {
        int e0 = __ldg(&buf[mb + g]);
        float4 x = __ldg(reinterpret_cast<const float4*>(g_e1) + (size_t)e0 * 4 + c);
        acc.x += x.x; acc.y += x.y; acc.z += x.z; acc.w += x.w;
    }
    if (mb + g < cnt) {
        int e0 = __ldg(&buf[mb + g]);
        float4 x = __ldg(reinterpret_cast<const float4*>(g_e1) + (size_t)e0 * 4 + c);
        acc.x += x.x; acc.y += x.y; acc.z += x.z; acc.w += x.w;
    }
#pragma unroll
    for (int st = 4; st < 32; st <<= 1) {
        acc.x += __shfl_xor_sync(0xFFFFFFFFu, acc.x, st);
        acc.y += __shfl_xor_sync(0xFFFFFFFFu, acc.y, st);
        acc.z += __shfl_xor_sync(0xFFFFFFFFu, acc.z, st);
        acc.w += __shfl_xor_sync(0xFFFFFFFFu, acc.w, st);
    }
    float invd = __frcp_rn(fmaxf((float)cnt, 1.f));
    float4 xx;   // lane holds x[4c..4c+3]
    xx.x = fmaxf(acc.x * invd + sB[c * 4 + 0], 0.f);
    xx.y = fmaxf(acc.y * invd + sB[c * 4 + 1], 0.f);
    xx.z = fmaxf(acc.z * invd + sB[c * 4 + 2], 0.f);
    xx.w = fmaxf(acc.w * invd + sB[c * 4 + 3], 0.f);

    float o0 = 0.f, o1 = 0.f;
#pragma unroll
    for (int k = 0; k < D_HID; k++) {
        int src = k >> 2;   // lane src has c == k/4
        float comp = (k & 3) == 0 ? xx.x : (k & 3) == 1 ? xx.y : (k & 3) == 2 ? xx.z : xx.w;
        float xk = __shfl_sync(0xFFFFFFFFu, comp, src);
        o0 += xk * sW[k * D_OUT + lane];
        if (lane < D_OUT - 32) o1 += xk * sW[k * D_OUT + 32 + lane];
    }
    g_XW2[(size_t)v * D_OUT + lane] = o0;
    if (lane < D_OUT - 32) g_XW2[(size_t)v * D_OUT + 32 + lane] = o1;
}

// ---------------- edge gather 2: warp/edge, 3 groups x 10-lane float4 --------
__global__ void edge_gather2_kernel(const float* __restrict__ w) {
    int warp = (blockIdx.x * blockDim.x + threadIdx.x) >> 5;
    int lane = threadIdx.x & 31;
    if (warp >= N_EDGES) return;
    int e = warp;
    int cnt = min(__ldg(&g_cnt_e[e]), PAD_E);
    int grp = lane / 10;          // 0..2 active, lanes 30,31 idle
    int gc  = lane - grp * 10;
    bool act = lane < 30;

    const int* buf = g_buf_e + (size_t)e * PAD_E;
    float4 acc = make_float4(0.f, 0.f, 0.f, 0.f);
    float wsum = 0.f;
    int mb = 0;
    for (; mb + 3 <= cnt; mb += 3) {
        if (act) {
            int v = __ldg(&buf[mb + grp]);
            float wv = __ldg(&w[v]);
            float4 x = __ldg(reinterpret_cast<const float4*>(g_XW2) + (size_t)v * 10 + gc);
            acc.x += wv * x.x; acc.y += wv * x.y; acc.z += wv * x.z; acc.w += wv * x.w;
            wsum += wv;
        }
    }
    if (act && grp < cnt - mb) {
        int v = __ldg(&buf[mb + grp]);
        float wv = __ldg(&w[v]);
        float4 x = __ldg(reinterpret_cast<const float4*>(g_XW2) + (size_t)v * 10 + gc);
        acc.x += wv * x.x; acc.y += wv * x.y; acc.z += wv * x.z; acc.w += wv * x.w;
        wsum += wv;
    }
    acc.x += __shfl_sync(0xFFFFFFFFu, acc.x, lane + 10) + __shfl_sync(0xFFFFFFFFu, acc.x, lane + 20);
    acc.y += __shfl_sync(0xFFFFFFFFu, acc.y, lane + 10) + __shfl_sync(0xFFFFFFFFu, acc.y, lane + 20);
    acc.z += __shfl_sync(0xFFFFFFFFu, acc.z, lane + 10) + __shfl_sync(0xFFFFFFFFu, acc.z, lane + 20);
    acc.w += __shfl_sync(0xFFFFFFFFu, acc.w, lane + 10) + __shfl_sync(0xFFFFFFFFu, acc.w, lane + 20);
    wsum  += __shfl_sync(0xFFFFFFFFu, wsum,  lane + 10) + __shfl_sync(0xFFFFFFFFu, wsum,  lane + 20);
    if (lane < 10) {
        float inv = __frcp_rn(fmaxf(wsum, 1e-6f));
        float4 r = make_float4(acc.x * inv, acc.y * inv, acc.z * inv, acc.w * inv);
        reinterpret_cast<float4*>(g_e2)[(size_t)e * 10 + lane] = r;
    }
}

// ---------------- node gather 2 + bias + log_softmax -> out ------------------
__global__ void node_gather2_fin_kernel(float* __restrict__ out,
                                        const float* __restrict__ b2) {
    int warp = (blockIdx.x * blockDim.x + threadIdx.x) >> 5;
    int lane = threadIdx.x & 31;
    if (warp >= N_NODES) return;
    int v = warp;
    int cnt = min(__ldg(&g_cnt_v[v]), PAD_V);
    int grp = lane / 10;
    int gc  = lane - grp * 10;
    bool act = lane < 30;

    const int* buf = g_buf_v + (size_t)v * PAD_V;
    float4 acc = make_float4(0.f, 0.f, 0.f, 0.f);
    int mb = 0;
    for (; mb + 3 <= cnt; mb += 3) {
        if (act) {
            int e0 = __ldg(&buf[mb + grp]);
            float4 x = __ldg(reinterpret_cast<const float4*>(g_e2) + (size_t)e0 * 10 + gc);
            acc.x += x.x; acc.y += x.y; acc.z += x.z; acc.w += x.w;
        }
    }
    if (act && grp < cnt - mb) {
        int e0 = __ldg(&buf[mb + grp]);
        float4 x = __ldg(reinterpret_cast<const float4*>(g_e2) + (size_t)e0 * 10 + gc);
        acc.x += x.x; acc.y += x.y; acc.z += x.z; acc.w += x.w;
    }
    acc.x += __shfl_sync(0xFFFFFFFFu, acc.x, lane + 10) + __shfl_sync(0xFFFFFFFFu, acc.x, lane + 20);
    acc.y += __shfl_sync(0xFFFFFFFFu, acc.y, lane + 10) + __shfl_sync(0xFFFFFFFFu, acc.y, lane + 20);
    acc.z += __shfl_sync(0xFFFFFFFFu, acc.z, lane + 10) + __shfl_sync(0xFFFFFFFFu, acc.z, lane + 20);
    acc.w += __shfl_sync(0xFFFFFFFFu, acc.w, lane + 10) + __shfl_sync(0xFFFFFFFFu, acc.w, lane + 20);

    float invd = __frcp_rn(fmaxf((float)cnt, 1.f));
    float4 val = make_float4(-INFINITY, -INFINITY, -INFINITY, -INFINITY);
    if (lane < 10) {
        float4 bb = __ldg(reinterpret_cast<const float4*>(b2) + lane);
        val.x = acc.x * invd + bb.x;
        val.y = acc.y * invd + bb.y;
        val.z = acc.z * invd + bb.z;
        val.w = acc.w * invd + bb.w;
    }
    float mx = fmaxf(fmaxf(val.x, val.y), fmaxf(val.z, val.w));
#pragma unroll
    for (int st = 8; st > 0; st >>= 1)
        mx = fmaxf(mx, __shfl_xor_sync(0xFFFFFFFFu, mx, st));    // lanes 0..15 all-reduce
    float s = (lane < 10)
        ? (__expf(val.x - mx) + __expf(val.y - mx) + __expf(val.z - mx) + __expf(val.w - mx))
        : 0.f;
#pragma unroll
    for (int st = 8; st > 0; st >>= 1)
        s += __shfl_xor_sync(0xFFFFFFFFu, s, st);
    float lse = mx + __logf(s);
    if (lane < 10) {
        float4 r = make_float4(val.x - lse, val.y - lse, val.z - lse, val.w - lse);
        reinterpret_cast<float4*>(out)[(size_t)v * 10 + lane] = r;
    }
}

// ---------------- launch ----------------
extern "C" void kernel_launch(void* const* d_in, const int* in_sizes, int n_in,
                              void* d_out, int out_size) {
    const float* H   = (const float*)d_in[0];
    const float* w   = (const float*)d_in[1];
    const int*   ni  = (const int*)  d_in[2];
    const int*   ei  = (const int*)  d_in[3];
    const float* W1  = (const float*)d_in[4];
    const float* b1  = (const float*)d_in[5];
    const float* W2  = (const float*)d_in[6];
    const float* b2  = (const float*)d_in[7];
    float*       out = (float*)d_out;

    const int T = 256;
    auto blocks = [](long n, int t) { return (int)((n + t - 1) / t); };

    zero_cnt_kernel<<<blocks(ZC, T), T>>>();
    fill_kernel<<<blocks(N_INC, T), T>>>(ni, ei);
    gemm1_kernel<<<blocks(N_NODES, T), T>>>(H, W1);

    edge_gather1_kernel<<<blocks((long)N_EDGES * 32, T), T>>>(w);
    node_gather1_gemm2_kernel<<<blocks((long)N_NODES * 32, T), T>>>(W2, b1);

    edge_gather2_kernel<<<blocks((long)N_EDGES * 32, T), T>>>(w);
    node_gather2_fin_kernel<<<blocks((long)N_NODES * 32, T), T>>>(out, b2);
}